// round 7
// baseline (speedup 1.0000x reference)
#include <cuda_runtime.h>
#include <cuda_bf16.h>

// out[b] = softmax_rows(X_b X_b^T), X: [4, 4096, 64] fp32.
// R6: fused (no 256MB scratch), 128x64 tiles @ 128 threads, 4 CTAs/SM.
//  k_zero, k0 split+norms, k0b shift m_i = |x_i|*max|x_j| (>= row max),
//  k1 stats: symmetric MMA, row+col partial exp-sums (in-register reductions),
//  k1b inv, k2 main: recompute MMA, write exp(s-m)*inv direct to out.
// Harness ptxas target is sm_103 (no 'a') -> portable ldmatrix + mma.sync.

#define NTOK 4096
#define DDIM 64
#define NB   4

__device__ __nv_bfloat16 g_hi[(size_t)NB * NTOK * DDIM];   // 4 MB
__device__ __nv_bfloat16 g_lo[(size_t)NB * NTOK * DDIM];   // 4 MB
__device__ float g_norm2[NB * NTOK];
__device__ float g_m    [NB * NTOK];
__device__ float g_inv  [NB * NTOK];
__device__ float g_part [(size_t)NB * NTOK * 64];          // 4 MB

#define SW128(off) ((off) ^ (((off) >> 3) & 0x70))

// smem layout (bytes): Ah@0(16K) Al@16K Bh@32K(8K) Bl@40K(8K)
// rowM@49152 rowI@49664 colM@50176 colI@50432 colred@50688(1K)  total 51712
// stage (main only) reuses [0, 33792)
#define OFF_AL   16384
#define OFF_BH   32768
#define OFF_BL   40960
#define OFF_ROWM 49152
#define OFF_ROWI 49664
#define OFF_COLM 50176
#define OFF_COLI 50432
#define OFF_CRED 50688
#define SMEM_BYTES 51712
#define STG_LD 132

__device__ __forceinline__ unsigned smem_u32(const void* p) {
    unsigned a;
    asm("{ .reg .u64 t; cvta.to.shared.u64 t, %1; cvt.u32.u64 %0, t; }"
        : "=r"(a) : "l"(p));
    return a;
}
__device__ __forceinline__ void ldsm4(unsigned* r, unsigned addr) {
    asm volatile("ldmatrix.sync.aligned.m8n8.x4.shared.b16 {%0,%1,%2,%3}, [%4];"
                 : "=r"(r[0]), "=r"(r[1]), "=r"(r[2]), "=r"(r[3]) : "r"(addr));
}
__device__ __forceinline__ void mma16816(float* d, const unsigned* a,
                                         unsigned b0, unsigned b1) {
    asm volatile(
        "mma.sync.aligned.m16n8k16.row.col.f32.bf16.bf16.f32 "
        "{%0,%1,%2,%3}, {%4,%5,%6,%7}, {%8,%9}, {%0,%1,%2,%3};"
        : "+f"(d[0]), "+f"(d[1]), "+f"(d[2]), "+f"(d[3])
        : "r"(a[0]), "r"(a[1]), "r"(a[2]), "r"(a[3]), "r"(b0), "r"(b1));
}

// triangular pair decode: p in [0,528) -> (ti<=tj), S(ti)=ti*(65-ti)/2
__device__ __forceinline__ void decode_pair(int p, int& ti, int& tj) {
    ti = (int)((65.0f - sqrtf(4225.0f - 8.0f * (float)p)) * 0.5f);
    while (ti * (65 - ti) / 2 > p) ti--;
    while ((ti + 1) * (64 - ti) / 2 <= p) ti++;
    tj = ti + (p - ti * (65 - ti) / 2);
}

// ---------------- small kernels ----------------
__global__ __launch_bounds__(256) void zero_part() {
    size_t i = ((size_t)blockIdx.x * 256 + threadIdx.x) * 4;
    *reinterpret_cast<float4*>(g_part + i) = make_float4(0.f, 0.f, 0.f, 0.f);
}

__global__ __launch_bounds__(256) void split_bf16(const float* __restrict__ X) {
    size_t gid = (size_t)blockIdx.x * blockDim.x + threadIdx.x;
    size_t i = gid * 4;
    float4 v = *reinterpret_cast<const float4*>(X + i);
    __nv_bfloat162 h01 = __floats2bfloat162_rn(v.x, v.y);
    __nv_bfloat162 h23 = __floats2bfloat162_rn(v.z, v.w);
    __nv_bfloat162 l01 = __floats2bfloat162_rn(v.x - __low2float(h01),
                                               v.y - __high2float(h01));
    __nv_bfloat162 l23 = __floats2bfloat162_rn(v.z - __low2float(h23),
                                               v.w - __high2float(h23));
    *reinterpret_cast<__nv_bfloat162*>(g_hi + i)     = h01;
    *reinterpret_cast<__nv_bfloat162*>(g_hi + i + 2) = h23;
    *reinterpret_cast<__nv_bfloat162*>(g_lo + i)     = l01;
    *reinterpret_cast<__nv_bfloat162*>(g_lo + i + 2) = l23;

    float p = v.x * v.x + v.y * v.y + v.z * v.z + v.w * v.w;
#pragma unroll
    for (int o = 1; o < 16; o <<= 1) p += __shfl_xor_sync(0xffffffffu, p, o);
    if ((threadIdx.x & 15) == 0) g_norm2[gid >> 4] = p;
}

__global__ __launch_bounds__(1024) void make_shift() {
    const int b = blockIdx.x, t = threadIdx.x;
    float n2[4], mx = 0.0f;
#pragma unroll
    for (int k = 0; k < 4; k++) {
        n2[k] = g_norm2[b * NTOK + t + k * 1024];
        mx = fmaxf(mx, n2[k]);
    }
    __shared__ float red[32];
#pragma unroll
    for (int o = 16; o > 0; o >>= 1) mx = fmaxf(mx, __shfl_xor_sync(~0u, mx, o));
    if ((t & 31) == 0) red[t >> 5] = mx;
    __syncthreads();
    if (t < 32) {
        float w = red[t];
#pragma unroll
        for (int o = 16; o > 0; o >>= 1) w = fmaxf(w, __shfl_xor_sync(~0u, w, o));
        red[t] = w;
    }
    __syncthreads();
    const float M2 = red[0];
#pragma unroll
    for (int k = 0; k < 4; k++)
        g_m[b * NTOK + t + k * 1024] = sqrtf(n2[k] * M2);
}

__global__ __launch_bounds__(256) void reduce_inv() {
    const int wid = threadIdx.x >> 5, lane = threadIdx.x & 31;
    const size_t row = (size_t)blockIdx.x * 8 + wid;
    const float* p = g_part + row * 64;
    float s = p[lane] + p[lane + 32];
#pragma unroll
    for (int o = 16; o > 0; o >>= 1) s += __shfl_xor_sync(~0u, s, o);
    if (lane == 0) g_inv[row] = 1.0f / s;
}

// ---------------- shared tile compute ----------------
template<int CH>
__device__ __forceinline__ void load_t(char* dst, const __nv_bfloat16* src, int tid) {
    const uint4* s = reinterpret_cast<const uint4*>(src);
#pragma unroll
    for (int it = 0; it < CH; it++) {
        int i = it * 128 + tid;
        unsigned off = (unsigned)i * 16u;
        *reinterpret_cast<uint4*>(dst + SW128(off)) = s[i];
    }
}

template<bool INV>
__device__ __forceinline__ void tile_compute(char* smem, unsigned sm, int tid,
                                             int wid, int lane, int ti, int tj,
                                             int half, int b, bool diag,
                                             float acc[2][8][4]) {
    const size_t gti = (size_t)b * NTOK + (size_t)ti * 128;
    const size_t gtj = (size_t)b * NTOK + (size_t)tj * 128 + half * 64;
    load_t<8>(smem,          g_hi + gti * DDIM, tid);
    load_t<8>(smem + OFF_AL, g_lo + gti * DDIM, tid);
    if (!diag) {
        load_t<4>(smem + OFF_BH, g_hi + gtj * DDIM, tid);
        load_t<4>(smem + OFF_BL, g_lo + gtj * DDIM, tid);
    }
    reinterpret_cast<float*>(smem + OFF_ROWM)[tid] = g_m[gti + tid];
    if (INV) reinterpret_cast<float*>(smem + OFF_ROWI)[tid] = g_inv[gti + tid];
    if (tid < 64) {
        reinterpret_cast<float*>(smem + OFF_COLM)[tid] = g_m[gtj + tid];
        if (INV) reinterpret_cast<float*>(smem + OFF_COLI)[tid] = g_inv[gtj + tid];
    }
    __syncthreads();

#pragma unroll
    for (int mf = 0; mf < 2; mf++)
#pragma unroll
        for (int nf = 0; nf < 8; nf++)
#pragma unroll
            for (int e = 0; e < 4; e++) acc[mf][nf][e] = 0.0f;

    const int mrow0 = wid * 32;
    const int lrow  = lane & 15;
    const int lkoff = (lane >> 4) * 8;
    const unsigned abH = sm, abL = sm + OFF_AL;
    const unsigned bbH = diag ? sm + half * 8192          : sm + OFF_BH;
    const unsigned bbL = diag ? sm + OFF_AL + half * 8192 : sm + OFF_BL;

#pragma unroll
    for (int ks = 0; ks < 4; ks++) {
        const unsigned kbyte = (unsigned)(ks * 16 + lkoff) * 2u;
        unsigned ah[2][4], al[2][4];
#pragma unroll
        for (int mf = 0; mf < 2; mf++) {
            unsigned byte = (unsigned)(mrow0 + mf * 16 + lrow) * 128u + kbyte;
            ldsm4(ah[mf], abH + SW128(byte));
            ldsm4(al[mf], abL + SW128(byte));
        }
#pragma unroll
        for (int nq = 0; nq < 4; nq++) {
            unsigned bh[4], bl[4];
            unsigned byte = (unsigned)(nq * 16 + lrow) * 128u + kbyte;
            ldsm4(bh, bbH + SW128(byte));
            ldsm4(bl, bbL + SW128(byte));
#pragma unroll
            for (int mf = 0; mf < 2; mf++) {
                float* d0 = acc[mf][nq * 2 + 0];
                float* d1 = acc[mf][nq * 2 + 1];
                mma16816(d0, ah[mf], bh[0], bh[2]);
                mma16816(d1, ah[mf], bh[1], bh[3]);
                mma16816(d0, ah[mf], bl[0], bl[2]);
                mma16816(d1, ah[mf], bl[1], bl[3]);
                mma16816(d0, al[mf], bh[0], bh[2]);
                mma16816(d1, al[mf], bh[1], bh[3]);
            }
        }
    }
}

// ---------------- k1: stats pass ----------------
__global__ __launch_bounds__(128, 4) void gemm_stats() {
    int ti, tj;
    decode_pair(blockIdx.x, ti, tj);
    const int half = blockIdx.y, b = blockIdx.z;
    const bool diag = (ti == tj);

    extern __shared__ __align__(1024) char smem[];
    const unsigned sm = smem_u32(smem);
    const int tid = threadIdx.x, wid = tid >> 5, lane = tid & 31;

    float acc[2][8][4];
    tile_compute<false>(smem, sm, tid, wid, lane, ti, tj, half, b, diag, acc);

    const float* rowM = reinterpret_cast<const float*>(smem + OFF_ROWM);
    const float* colM = reinterpret_cast<const float*>(smem + OFF_COLM);
    float* cred = reinterpret_cast<float*>(smem + OFF_CRED);

    const int mrow0 = wid * 32;
    const int fr = lane >> 2;
    const int fc = (lane & 3) * 2;
    const size_t gti = (size_t)b * NTOK + (size_t)ti * 128;
    const size_t gtj = (size_t)b * NTOK + (size_t)tj * 128 + half * 64;

    // --- row-side: sums over this CTA's 64 cols, shift m_row ---
    {
        float rs[4];
#pragma unroll
        for (int mf = 0; mf < 2; mf++) {
            const float m0 = rowM[mrow0 + mf * 16 + fr];
            const float m1 = rowM[mrow0 + mf * 16 + fr + 8];
            float s0 = 0.f, s1 = 0.f;
#pragma unroll
            for (int nf = 0; nf < 8; nf++) {
                s0 += __expf(acc[mf][nf][0] - m0) + __expf(acc[mf][nf][1] - m0);
                s1 += __expf(acc[mf][nf][2] - m1) + __expf(acc[mf][nf][3] - m1);
            }
            rs[mf * 2] = s0; rs[mf * 2 + 1] = s1;
        }
#pragma unroll
        for (int k = 0; k < 4; k++) {
            rs[k] += __shfl_xor_sync(~0u, rs[k], 1);
            rs[k] += __shfl_xor_sync(~0u, rs[k], 2);
        }
        if ((lane & 3) == 0) {
            const int slot = tj * 2 + half;
#pragma unroll
            for (int k = 0; k < 4; k++) {
                int r = mrow0 + (k >> 1) * 16 + fr + (k & 1) * 8;
                g_part[(gti + r) * 64 + slot] = rs[k];
            }
        }
    }

    if (diag) return;

    // --- col-side: sums over this CTA's 128 rows, shift m_col, in registers ---
    {
        float cp0[8], cp1[8];
#pragma unroll
        for (int nf = 0; nf < 8; nf++) {
            const float mc0 = colM[nf * 8 + fc];
            const float mc1 = colM[nf * 8 + fc + 1];
            float p0 = 0.f, p1 = 0.f;
#pragma unroll
            for (int mf = 0; mf < 2; mf++) {
                p0 += __expf(acc[mf][nf][0] - mc0) + __expf(acc[mf][nf][2] - mc0);
                p1 += __expf(acc[mf][nf][1] - mc1) + __expf(acc[mf][nf][3] - mc1);
            }
            cp0[nf] = p0; cp1[nf] = p1;
        }
#pragma unroll
        for (int nf = 0; nf < 8; nf++) {
#pragma unroll
            for (int o = 4; o <= 16; o <<= 1) {
                cp0[nf] += __shfl_xor_sync(~0u, cp0[nf], o);
                cp1[nf] += __shfl_xor_sync(~0u, cp1[nf], o);
            }
        }
        if (lane < 4) {
#pragma unroll
            for (int nf = 0; nf < 8; nf++) {
                cred[wid * 64 + nf * 8 + fc]     = cp0[nf];
                cred[wid * 64 + nf * 8 + fc + 1] = cp1[nf];
            }
        }
        __syncthreads();
        if (tid < 64) {
            float s = cred[tid] + cred[64 + tid] + cred[128 + tid] + cred[192 + tid];
            g_part[(gtj + tid) * 64 + 2 * ti] = s;
        }
    }
}

// ---------------- k2: main pass ----------------
__global__ __launch_bounds__(128, 4) void gemm_main(float* __restrict__ out) {
    int ti, tj;
    decode_pair(blockIdx.x, ti, tj);
    const int half = blockIdx.y, b = blockIdx.z;
    const bool diag = (ti == tj);

    extern __shared__ __align__(1024) char smem[];
    float* stage = reinterpret_cast<float*>(smem);
    const unsigned sm = smem_u32(smem);
    const int tid = threadIdx.x, wid = tid >> 5, lane = tid & 31;

    float acc[2][8][4];
    tile_compute<true>(smem, sm, tid, wid, lane, ti, tj, half, b, diag, acc);

    const float* rowM = reinterpret_cast<const float*>(smem + OFF_ROWM);
    const float* rowI = reinterpret_cast<const float*>(smem + OFF_ROWI);
    const float* colM = reinterpret_cast<const float*>(smem + OFF_COLM);
    const float* colI = reinterpret_cast<const float*>(smem + OFF_COLI);

    const int mrow0 = wid * 32;
    const int fr = lane >> 2;
    const int fc = (lane & 3) * 2;
    float* Ob = out + (size_t)b * NTOK * NTOK;

    // --- normal tile: direct normalized streaming stores ---
    {
        float* dst = Ob + (size_t)(ti * 128) * NTOK + tj * 128 + half * 64;
#pragma unroll
        for (int mf = 0; mf < 2; mf++) {
            const int r0 = mrow0 + mf * 16 + fr;
            const float m0 = rowM[r0],     i0 = rowI[r0];
            const float m1 = rowM[r0 + 8], i1 = rowI[r0 + 8];
#pragma unroll
            for (int nf = 0; nf < 8; nf++) {
                const int c = nf * 8 + fc;
                __stcs(reinterpret_cast<float2*>(dst + (size_t)r0 * NTOK + c),
                       make_float2(__expf(acc[mf][nf][0] - m0) * i0,
                                   __expf(acc[mf][nf][1] - m0) * i0));
                __stcs(reinterpret_cast<float2*>(dst + (size_t)(r0 + 8) * NTOK + c),
                       make_float2(__expf(acc[mf][nf][2] - m1) * i1,
                                   __expf(acc[mf][nf][3] - m1) * i1));
            }
        }
    }

    if (diag) return;

    // --- mirror: normalize with col shift at stage-write, then coalesced copy ---
    __syncthreads();  // all warps done reading operands
#pragma unroll
    for (int mf = 0; mf < 2; mf++) {
        const int r0 = mrow0 + mf * 16 + fr;
#pragma unroll
        for (int nf = 0; nf < 8; nf++) {
            const int c0 = nf * 8 + fc;
            const float mc0 = colM[c0],     ic0 = colI[c0];
            const float mc1 = colM[c0 + 1], ic1 = colI[c0 + 1];
            stage[(size_t)c0 * STG_LD + r0]           = __expf(acc[mf][nf][0] - mc0) * ic0;
            stage[(size_t)c0 * STG_LD + r0 + 8]       = __expf(acc[mf][nf][2] - mc0) * ic0;
            stage[(size_t)(c0 + 1) * STG_LD + r0]     = __expf(acc[mf][nf][1] - mc1) * ic1;
            stage[(size_t)(c0 + 1) * STG_LD + r0 + 8] = __expf(acc[mf][nf][3] - mc1) * ic1;
        }
    }
    __syncthreads();
    {
        float* dst = Ob + (size_t)(tj * 128 + half * 64) * NTOK + ti * 128;
        const int c4 = (tid & 31) * 4, rq = tid >> 5;
#pragma unroll
        for (int it = 0; it < 16; it++) {
            const int sr = rq + it * 4;
            float4 v = *reinterpret_cast<const float4*>(stage + (size_t)sr * STG_LD + c4);
            __stcs(reinterpret_cast<float4*>(dst + (size_t)sr * NTOK + c4), v);
        }
    }
}

extern "C" void kernel_launch(void* const* d_in, const int* in_sizes, int n_in,
                              void* d_out, int out_size) {
    const float* X = (const float*)d_in[0];
    float* out     = (float*)d_out;
    (void)in_sizes; (void)n_in; (void)out_size;

    cudaFuncSetAttribute(gemm_stats, cudaFuncAttributeMaxDynamicSharedMemorySize,
                         SMEM_BYTES);
    cudaFuncSetAttribute(gemm_main, cudaFuncAttributeMaxDynamicSharedMemorySize,
                         SMEM_BYTES);

    zero_part<<<1024, 256>>>();
    split_bf16<<<1024, 256>>>(X);
    make_shift<<<NB, 1024>>>();
    gemm_stats<<<dim3(528, 2, NB), 128, SMEM_BYTES>>>();
    reduce_inv<<<NB * NTOK / 8, 256>>>();
    gemm_main<<<dim3(528, 2, NB), 128, SMEM_BYTES>>>(out);
}

// round 8
// speedup vs baseline: 1.0052x; 1.0052x over previous
#include <cuda_runtime.h>
#include <cuda_bf16.h>

// out[b] = softmax_rows(X_b X_b^T), X: [4, 4096, 64] fp32.
// R8: fused, 128x64 tiles @ 128 thr, 4 CTAs/SM. MMA inner loop reordered into
//     term groups (hi*hi | hi*lo | lo*hi) so each accumulator is touched once
//     per group -> no HMMA RAW chains. zero_part dropped (masked reduce).
// Harness ptxas target is sm_103 (no 'a') -> portable ldmatrix + mma.sync.

#define NTOK 4096
#define DDIM 64
#define NB   4

__device__ __nv_bfloat16 g_hi[(size_t)NB * NTOK * DDIM];   // 4 MB
__device__ __nv_bfloat16 g_lo[(size_t)NB * NTOK * DDIM];   // 4 MB
__device__ float g_norm2[NB * NTOK];
__device__ float g_m    [NB * NTOK];
__device__ float g_inv  [NB * NTOK];
__device__ float g_part [(size_t)NB * NTOK * 64];          // 4 MB

#define SW128(off) ((off) ^ (((off) >> 3) & 0x70))

// smem layout (bytes): Ah@0(16K) Al@16K Bh@32K(8K) Bl@40K(8K)
// rowM@49152 rowI@49664 colM@50176 colI@50432 colred@50688(1K)
// stage (main mirror) reuses [0, 33792)
#define OFF_AL   16384
#define OFF_BH   32768
#define OFF_BL   40960
#define OFF_ROWM 49152
#define OFF_ROWI 49664
#define OFF_COLM 50176
#define OFF_COLI 50432
#define OFF_CRED 50688
#define SMEM_BYTES 51712
#define STG_LD 132

__device__ __forceinline__ unsigned smem_u32(const void* p) {
    unsigned a;
    asm("{ .reg .u64 t; cvta.to.shared.u64 t, %1; cvt.u32.u64 %0, t; }"
        : "=r"(a) : "l"(p));
    return a;
}
__device__ __forceinline__ void ldsm4(unsigned* r, unsigned addr) {
    asm volatile("ldmatrix.sync.aligned.m8n8.x4.shared.b16 {%0,%1,%2,%3}, [%4];"
                 : "=r"(r[0]), "=r"(r[1]), "=r"(r[2]), "=r"(r[3]) : "r"(addr));
}
__device__ __forceinline__ void mma16816(float* d, const unsigned* a,
                                         unsigned b0, unsigned b1) {
    asm volatile(
        "mma.sync.aligned.m16n8k16.row.col.f32.bf16.bf16.f32 "
        "{%0,%1,%2,%3}, {%4,%5,%6,%7}, {%8,%9}, {%0,%1,%2,%3};"
        : "+f"(d[0]), "+f"(d[1]), "+f"(d[2]), "+f"(d[3])
        : "r"(a[0]), "r"(a[1]), "r"(a[2]), "r"(a[3]), "r"(b0), "r"(b1));
}

__device__ __forceinline__ void decode_pair(int p, int& ti, int& tj) {
    ti = (int)((65.0f - sqrtf(4225.0f - 8.0f * (float)p)) * 0.5f);
    while (ti * (65 - ti) / 2 > p) ti--;
    while ((ti + 1) * (64 - ti) / 2 <= p) ti++;
    tj = ti + (p - ti * (65 - ti) / 2);
}

// ---------------- small kernels ----------------
__global__ __launch_bounds__(256) void split_bf16(const float* __restrict__ X) {
    size_t gid = (size_t)blockIdx.x * blockDim.x + threadIdx.x;
    size_t i = gid * 4;
    float4 v = *reinterpret_cast<const float4*>(X + i);
    __nv_bfloat162 h01 = __floats2bfloat162_rn(v.x, v.y);
    __nv_bfloat162 h23 = __floats2bfloat162_rn(v.z, v.w);
    __nv_bfloat162 l01 = __floats2bfloat162_rn(v.x - __low2float(h01),
                                               v.y - __high2float(h01));
    __nv_bfloat162 l23 = __floats2bfloat162_rn(v.z - __low2float(h23),
                                               v.w - __high2float(h23));
    *reinterpret_cast<__nv_bfloat162*>(g_hi + i)     = h01;
    *reinterpret_cast<__nv_bfloat162*>(g_hi + i + 2) = h23;
    *reinterpret_cast<__nv_bfloat162*>(g_lo + i)     = l01;
    *reinterpret_cast<__nv_bfloat162*>(g_lo + i + 2) = l23;

    float p = v.x * v.x + v.y * v.y + v.z * v.z + v.w * v.w;
#pragma unroll
    for (int o = 1; o < 16; o <<= 1) p += __shfl_xor_sync(0xffffffffu, p, o);
    if ((threadIdx.x & 15) == 0) g_norm2[gid >> 4] = p;
}

__global__ __launch_bounds__(1024) void make_shift() {
    const int b = blockIdx.x, t = threadIdx.x;
    float n2[4], mx = 0.0f;
#pragma unroll
    for (int k = 0; k < 4; k++) {
        n2[k] = g_norm2[b * NTOK + t + k * 1024];
        mx = fmaxf(mx, n2[k]);
    }
    __shared__ float red[32];
#pragma unroll
    for (int o = 16; o > 0; o >>= 1) mx = fmaxf(mx, __shfl_xor_sync(~0u, mx, o));
    if ((t & 31) == 0) red[t >> 5] = mx;
    __syncthreads();
    if (t < 32) {
        float w = red[t];
#pragma unroll
        for (int o = 16; o > 0; o >>= 1) w = fmaxf(w, __shfl_xor_sync(~0u, w, o));
        red[t] = w;
    }
    __syncthreads();
    const float M2 = red[0];
#pragma unroll
    for (int k = 0; k < 4; k++)
        g_m[b * NTOK + t + k * 1024] = sqrtf(n2[k] * M2);
}

// valid slots for a row in tile t: [0,t) (col-side) and [2t,64) (row-side)
__global__ __launch_bounds__(256) void reduce_inv() {
    const int wid = threadIdx.x >> 5, lane = threadIdx.x & 31;
    const size_t row = (size_t)blockIdx.x * 8 + wid;
    const int t = ((int)row & (NTOK - 1)) >> 7;
    const float* p = g_part + row * 64;
    float v0 = (lane < t || lane >= 2 * t) ? p[lane] : 0.0f;
    float v1 = (lane + 32 >= 2 * t) ? p[lane + 32] : 0.0f;
    float s = v0 + v1;
#pragma unroll
    for (int o = 16; o > 0; o >>= 1) s += __shfl_xor_sync(~0u, s, o);
    if (lane == 0) g_inv[row] = 1.0f / s;
}

// ---------------- shared tile compute ----------------
template<int CH>
__device__ __forceinline__ void load_t(char* dst, const __nv_bfloat16* src, int tid) {
    const uint4* s = reinterpret_cast<const uint4*>(src);
#pragma unroll
    for (int it = 0; it < CH; it++) {
        int i = it * 128 + tid;
        unsigned off = (unsigned)i * 16u;
        *reinterpret_cast<uint4*>(dst + SW128(off)) = s[i];
    }
}

template<bool INV>
__device__ __forceinline__ void tile_compute(char* smem, unsigned sm, int tid,
                                             int wid, int lane, int ti, int tj,
                                             int half, int b, bool diag,
                                             float acc[2][8][4]) {
    const size_t gti = (size_t)b * NTOK + (size_t)ti * 128;
    const size_t gtj = (size_t)b * NTOK + (size_t)tj * 128 + half * 64;
    load_t<8>(smem,          g_hi + gti * DDIM, tid);
    load_t<8>(smem + OFF_AL, g_lo + gti * DDIM, tid);
    if (!diag) {
        load_t<4>(smem + OFF_BH, g_hi + gtj * DDIM, tid);
        load_t<4>(smem + OFF_BL, g_lo + gtj * DDIM, tid);
    }
    reinterpret_cast<float*>(smem + OFF_ROWM)[tid] = g_m[gti + tid];
    if (INV) reinterpret_cast<float*>(smem + OFF_ROWI)[tid] = g_inv[gti + tid];
    if (tid < 64) {
        reinterpret_cast<float*>(smem + OFF_COLM)[tid] = g_m[gtj + tid];
        if (INV) reinterpret_cast<float*>(smem + OFF_COLI)[tid] = g_inv[gtj + tid];
    }
    __syncthreads();

#pragma unroll
    for (int mf = 0; mf < 2; mf++)
#pragma unroll
        for (int nf = 0; nf < 8; nf++)
#pragma unroll
            for (int e = 0; e < 4; e++) acc[mf][nf][e] = 0.0f;

    const int mrow0 = wid * 32;
    const int lrow  = lane & 15;
    const int lkoff = (lane >> 4) * 8;
    const unsigned abH = sm, abL = sm + OFF_AL;
    const unsigned bbH = diag ? sm + half * 8192          : sm + OFF_BH;
    const unsigned bbL = diag ? sm + OFF_AL + half * 8192 : sm + OFF_BL;

    // per-thread row bases + swizzle XOR constants (kb < 128 so swizzle
    // reduces to XOR with (row&7)<<4)
    unsigned arow[2], axor[2], brow[4], bxor[4];
#pragma unroll
    for (int mf = 0; mf < 2; mf++) {
        arow[mf] = (unsigned)(mrow0 + mf * 16 + lrow) * 128u;
        axor[mf] = (((mrow0 + mf * 16 + lrow) & 7) << 4);
    }
#pragma unroll
    for (int nq = 0; nq < 4; nq++) {
        brow[nq] = (unsigned)(nq * 16 + lrow) * 128u;
        bxor[nq] = (((nq * 16 + lrow) & 7) << 4);
    }

#pragma unroll
    for (int ks = 0; ks < 4; ks++) {
        const unsigned kb = (unsigned)(ks * 16 + lkoff) * 2u;
        unsigned ah[2][4], al[2][4], bh[4][4], bl[4][4];
        // load hi frags
#pragma unroll
        for (int mf = 0; mf < 2; mf++)
            ldsm4(ah[mf], abH + arow[mf] + (kb ^ axor[mf]));
#pragma unroll
        for (int nq = 0; nq < 4; nq++)
            ldsm4(bh[nq], bbH + brow[nq] + (kb ^ bxor[nq]));
        // group 1: hi*hi (each acc touched once)
#pragma unroll
        for (int nq = 0; nq < 4; nq++)
#pragma unroll
            for (int mf = 0; mf < 2; mf++) {
                mma16816(acc[mf][nq * 2 + 0], ah[mf], bh[nq][0], bh[nq][2]);
                mma16816(acc[mf][nq * 2 + 1], ah[mf], bh[nq][1], bh[nq][3]);
            }
        // load lo frags (hidden under group 1 latency)
#pragma unroll
        for (int mf = 0; mf < 2; mf++)
            ldsm4(al[mf], abL + arow[mf] + (kb ^ axor[mf]));
#pragma unroll
        for (int nq = 0; nq < 4; nq++)
            ldsm4(bl[nq], bbL + brow[nq] + (kb ^ bxor[nq]));
        // group 2: hi*lo
#pragma unroll
        for (int nq = 0; nq < 4; nq++)
#pragma unroll
            for (int mf = 0; mf < 2; mf++) {
                mma16816(acc[mf][nq * 2 + 0], ah[mf], bl[nq][0], bl[nq][2]);
                mma16816(acc[mf][nq * 2 + 1], ah[mf], bl[nq][1], bl[nq][3]);
            }
        // group 3: lo*hi
#pragma unroll
        for (int nq = 0; nq < 4; nq++)
#pragma unroll
            for (int mf = 0; mf < 2; mf++) {
                mma16816(acc[mf][nq * 2 + 0], al[mf], bh[nq][0], bh[nq][2]);
                mma16816(acc[mf][nq * 2 + 1], al[mf], bh[nq][1], bh[nq][3]);
            }
    }
}

// ---------------- k1: stats pass ----------------
__global__ __launch_bounds__(128, 4) void gemm_stats() {
    int ti, tj;
    decode_pair(blockIdx.x, ti, tj);
    const int half = blockIdx.y, b = blockIdx.z;
    const bool diag = (ti == tj);

    extern __shared__ __align__(1024) char smem[];
    const unsigned sm = smem_u32(smem);
    const int tid = threadIdx.x, wid = tid >> 5, lane = tid & 31;

    float acc[2][8][4];
    tile_compute<false>(smem, sm, tid, wid, lane, ti, tj, half, b, diag, acc);

    const float* rowM = reinterpret_cast<const float*>(smem + OFF_ROWM);
    const float* colM = reinterpret_cast<const float*>(smem + OFF_COLM);
    float* cred = reinterpret_cast<float*>(smem + OFF_CRED);

    const int mrow0 = wid * 32;
    const int fr = lane >> 2;
    const int fc = (lane & 3) * 2;
    const size_t gti = (size_t)b * NTOK + (size_t)ti * 128;
    const size_t gtj = (size_t)b * NTOK + (size_t)tj * 128 + half * 64;

    // --- row-side: sums over this CTA's 64 cols, shift m_row ---
    {
        float rs[4];
#pragma unroll
        for (int mf = 0; mf < 2; mf++) {
            const float m0 = rowM[mrow0 + mf * 16 + fr];
            const float m1 = rowM[mrow0 + mf * 16 + fr + 8];
            float s0 = 0.f, s1 = 0.f;
#pragma unroll
            for (int nf = 0; nf < 8; nf++) {
                s0 += __expf(acc[mf][nf][0] - m0) + __expf(acc[mf][nf][1] - m0);
                s1 += __expf(acc[mf][nf][2] - m1) + __expf(acc[mf][nf][3] - m1);
            }
            rs[mf * 2] = s0; rs[mf * 2 + 1] = s1;
        }
#pragma unroll
        for (int k = 0; k < 4; k++) {
            rs[k] += __shfl_xor_sync(~0u, rs[k], 1);
            rs[k] += __shfl_xor_sync(~0u, rs[k], 2);
        }
        if ((lane & 3) == 0) {
            const int slot = tj * 2 + half;   // in [2*ti, 64)
#pragma unroll
            for (int k = 0; k < 4; k++) {
                int r = mrow0 + (k >> 1) * 16 + fr + (k & 1) * 8;
                g_part[(gti + r) * 64 + slot] = rs[k];
            }
        }
    }

    if (diag) return;

    // --- col-side: sums over this CTA's 128 rows, shift m_col ---
    {
        float cp0[8], cp1[8];
#pragma unroll
        for (int nf = 0; nf < 8; nf++) {
            const float mc0 = colM[nf * 8 + fc];
            const float mc1 = colM[nf * 8 + fc + 1];
            float p0 = 0.f, p1 = 0.f;
#pragma unroll
            for (int mf = 0; mf < 2; mf++) {
                p0 += __expf(acc[mf][nf][0] - mc0) + __expf(acc[mf][nf][2] - mc0);
                p1 += __expf(acc[mf][nf][1] - mc1) + __expf(acc[mf][nf][3] - mc1);
            }
            cp0[nf] = p0; cp1[nf] = p1;
        }
#pragma unroll
        for (int nf = 0; nf < 8; nf++) {
#pragma unroll
            for (int o = 4; o <= 16; o <<= 1) {
                cp0[nf] += __shfl_xor_sync(~0u, cp0[nf], o);
                cp1[nf] += __shfl_xor_sync(~0u, cp1[nf], o);
            }
        }
        if (lane < 4) {
#pragma unroll
            for (int nf = 0; nf < 8; nf++) {
                cred[wid * 64 + nf * 8 + fc]     = cp0[nf];
                cred[wid * 64 + nf * 8 + fc + 1] = cp1[nf];
            }
        }
        __syncthreads();
        if (tid < 64) {
            float s = cred[tid] + cred[64 + tid] + cred[128 + tid] + cred[192 + tid];
            g_part[(gtj + tid) * 64 + ti] = s;   // slot ti in [0, tj)
        }
    }
}

// ---------------- k2: main pass ----------------
__global__ __launch_bounds__(128, 4) void gemm_main(float* __restrict__ out) {
    int ti, tj;
    decode_pair(blockIdx.x, ti, tj);
    const int half = blockIdx.y, b = blockIdx.z;
    const bool diag = (ti == tj);

    extern __shared__ __align__(1024) char smem[];
    float* stage = reinterpret_cast<float*>(smem);
    const unsigned sm = smem_u32(smem);
    const int tid = threadIdx.x, wid = tid >> 5, lane = tid & 31;

    float acc[2][8][4];
    tile_compute<true>(smem, sm, tid, wid, lane, ti, tj, half, b, diag, acc);

    const float* rowM = reinterpret_cast<const float*>(smem + OFF_ROWM);
    const float* rowI = reinterpret_cast<const float*>(smem + OFF_ROWI);
    const float* colM = reinterpret_cast<const float*>(smem + OFF_COLM);
    const float* colI = reinterpret_cast<const float*>(smem + OFF_COLI);

    const int mrow0 = wid * 32;
    const int fr = lane >> 2;
    const int fc = (lane & 3) * 2;
    float* Ob = out + (size_t)b * NTOK * NTOK;

    // --- normal tile: direct normalized streaming stores ---
    {
        float* dst = Ob + (size_t)(ti * 128) * NTOK + tj * 128 + half * 64;
#pragma unroll
        for (int mf = 0; mf < 2; mf++) {
            const int r0 = mrow0 + mf * 16 + fr;
            const float m0 = rowM[r0],     i0 = rowI[r0];
            const float m1 = rowM[r0 + 8], i1 = rowI[r0 + 8];
#pragma unroll
            for (int nf = 0; nf < 8; nf++) {
                const int c = nf * 8 + fc;
                __stcs(reinterpret_cast<float2*>(dst + (size_t)r0 * NTOK + c),
                       make_float2(__expf(acc[mf][nf][0] - m0) * i0,
                                   __expf(acc[mf][nf][1] - m0) * i0));
                __stcs(reinterpret_cast<float2*>(dst + (size_t)(r0 + 8) * NTOK + c),
                       make_float2(__expf(acc[mf][nf][2] - m1) * i1,
                                   __expf(acc[mf][nf][3] - m1) * i1));
            }
        }
    }

    if (diag) return;

    // --- mirror: normalize with col shift at stage-write, coalesced copy ---
    __syncthreads();
#pragma unroll
    for (int mf = 0; mf < 2; mf++) {
        const int r0 = mrow0 + mf * 16 + fr;
#pragma unroll
        for (int nf = 0; nf < 8; nf++) {
            const int c0 = nf * 8 + fc;
            const float mc0 = colM[c0],     ic0 = colI[c0];
            const float mc1 = colM[c0 + 1], ic1 = colI[c0 + 1];
            stage[(size_t)c0 * STG_LD + r0]           = __expf(acc[mf][nf][0] - mc0) * ic0;
            stage[(size_t)c0 * STG_LD + r0 + 8]       = __expf(acc[mf][nf][2] - mc0) * ic0;
            stage[(size_t)(c0 + 1) * STG_LD + r0]     = __expf(acc[mf][nf][1] - mc1) * ic1;
            stage[(size_t)(c0 + 1) * STG_LD + r0 + 8] = __expf(acc[mf][nf][3] - mc1) * ic1;
        }
    }
    __syncthreads();
    {
        float* dst = Ob + (size_t)(tj * 128 + half * 64) * NTOK + ti * 128;
        const int c4 = (tid & 31) * 4, rq = tid >> 5;
#pragma unroll
        for (int it = 0; it < 16; it++) {
            const int sr = rq + it * 4;
            float4 v = *reinterpret_cast<const float4*>(stage + (size_t)sr * STG_LD + c4);
            __stcs(reinterpret_cast<float4*>(dst + (size_t)sr * NTOK + c4), v);
        }
    }
}

extern "C" void kernel_launch(void* const* d_in, const int* in_sizes, int n_in,
                              void* d_out, int out_size) {
    const float* X = (const float*)d_in[0];
    float* out     = (float*)d_out;
    (void)in_sizes; (void)n_in; (void)out_size;

    cudaFuncSetAttribute(gemm_stats, cudaFuncAttributeMaxDynamicSharedMemorySize,
                         SMEM_BYTES);
    cudaFuncSetAttribute(gemm_main, cudaFuncAttributeMaxDynamicSharedMemorySize,
                         SMEM_BYTES);

    split_bf16<<<1024, 256>>>(X);
    make_shift<<<NB, 1024>>>();
    gemm_stats<<<dim3(528, 2, NB), 128, SMEM_BYTES>>>();
    reduce_inv<<<NB * NTOK / 8, 256>>>();
    gemm_main<<<dim3(528, 2, NB), 128, SMEM_BYTES>>>(out);
}